// round 11
// baseline (speedup 1.0000x reference)
#include <cuda_runtime.h>
#include <cuda_fp16.h>
#include <cstdint>

#define T_TOK 8192
#define NEXP 8
#define DIN 1024
#define DH 4096
#define DOUT 1024

#define BM 128
#define BN 256
#define BK 32                    // fp16 elems per K-chunk
#define ROWB 80                  // padded smem row bytes -> conflict-free ldmatrix
#define A_STG (BM * ROWB)        // 10240
#define B_STG (BN * ROWB)        // 20480
#define STG (A_STG + B_STG)      // 30720
#define NS 4
#define SMEM_BYTES (NS * STG)    // 122880

// ---- device globals (no allocations allowed) ----
__device__ int    g_cnt[NEXP];
__device__ int    g_base[NEXP];
__device__ int    g_tok[NEXP * T_TOK];
__device__ float  g_wt [NEXP * T_TOK];
__device__ __half g_xh  [(size_t)T_TOK * DIN];            // 16 MB
__device__ __half g_Hh  [(size_t)(2 * T_TOK) * DH];       // 128 MB
__device__ __half g_W1th[(size_t)NEXP * DH * DIN];        // 64 MB  [e][n][k]
__device__ __half g_W2th[(size_t)NEXP * DOUT * DH];       // 64 MB  [e][o][h]

// ===========================================================================
// PTX helpers (base ISA only: cp.async / ldmatrix / mma.sync)
// ===========================================================================
__device__ __forceinline__ uint32_t smem_u32(const void* p) {
    uint32_t a;
    asm("{ .reg .u64 t; cvta.to.shared.u64 t, %1; cvt.u32.u64 %0, t; }"
        : "=r"(a) : "l"(p));
    return a;
}
#define CP16(dst, src) \
    asm volatile("cp.async.cg.shared.global [%0], [%1], 16;" \
        :: "r"(dst), "l"(src))
#define CP_COMMIT() asm volatile("cp.async.commit_group;" ::: "memory")
#define CP_WAIT2()  asm volatile("cp.async.wait_group 2;" ::: "memory")
#define LDSM4(r, addr) \
    asm volatile("ldmatrix.sync.aligned.m8n8.x4.shared.b16 {%0,%1,%2,%3}, [%4];" \
        : "=r"((r)[0]), "=r"((r)[1]), "=r"((r)[2]), "=r"((r)[3]) : "r"(addr))
#define MMA16816(c, a, b0v, b1v) \
    asm volatile("mma.sync.aligned.m16n8k16.row.col.f32.f16.f16.f32 " \
        "{%0,%1,%2,%3}, {%4,%5,%6,%7}, {%8,%9}, {%0,%1,%2,%3};" \
        : "+f"((c)[0]), "+f"((c)[1]), "+f"((c)[2]), "+f"((c)[3]) \
        : "r"((a)[0]), "r"((a)[1]), "r"((a)[2]), "r"((a)[3]), "r"(b0v), "r"(b1v))

// ===========================================================================
// small kernels
// ===========================================================================
__global__ void zero_kernel(float* __restrict__ out, size_t n) {
    size_t i = (size_t)blockIdx.x * blockDim.x + threadIdx.x;
    size_t stride = (size_t)gridDim.x * blockDim.x;
    for (; i < n; i += stride) out[i] = 0.f;
    if (blockIdx.x == 0 && threadIdx.x < NEXP) g_cnt[threadIdx.x] = 0;
}

__global__ void gate_kernel(const float* __restrict__ x,
                            const float* __restrict__ Wg,
                            const float* __restrict__ bg) {
    int t = (int)((blockIdx.x * blockDim.x + threadIdx.x) >> 5);
    int lane = threadIdx.x & 31;
    if (t >= T_TOK) return;
    const float* xr = x + (size_t)t * DIN;
    float acc[NEXP];
#pragma unroll
    for (int e = 0; e < NEXP; e++) acc[e] = 0.f;
    for (int k = lane; k < DIN; k += 32) {
        float xv = xr[k];
        const float4* wr = (const float4*)(Wg + (size_t)k * NEXP);
        float4 w0 = wr[0], w1 = wr[1];
        acc[0] += xv * w0.x; acc[1] += xv * w0.y;
        acc[2] += xv * w0.z; acc[3] += xv * w0.w;
        acc[4] += xv * w1.x; acc[5] += xv * w1.y;
        acc[6] += xv * w1.z; acc[7] += xv * w1.w;
    }
#pragma unroll
    for (int e = 0; e < NEXP; e++) {
#pragma unroll
        for (int off = 16; off; off >>= 1)
            acc[e] += __shfl_down_sync(0xffffffffu, acc[e], off);
    }
    if (lane == 0) {
#pragma unroll
        for (int e = 0; e < NEXP; e++) acc[e] += bg[e];
        int i0 = 0; float v0 = acc[0];
#pragma unroll
        for (int e = 1; e < NEXP; e++) if (acc[e] > v0) { v0 = acc[e]; i0 = e; }
        int i1 = -1; float v1 = -3.4e38f;
#pragma unroll
        for (int e = 0; e < NEXP; e++)
            if (e != i0 && acc[e] > v1) { v1 = acc[e]; i1 = e; }
        float w0 = 1.f / (1.f + expf(v1 - v0));
        float w1 = 1.f - w0;
        int s0 = atomicAdd(&g_cnt[i0], 1);
        g_tok[i0 * T_TOK + s0] = t; g_wt[i0 * T_TOK + s0] = w0;
        int s1 = atomicAdd(&g_cnt[i1], 1);
        g_tok[i1 * T_TOK + s1] = t; g_wt[i1 * T_TOK + s1] = w1;
    }
}

__global__ void prefix_kernel() {
    if (threadIdx.x == 0) {
        int s = 0;
#pragma unroll
        for (int e = 0; e < NEXP; e++) { g_base[e] = s; s += g_cnt[e]; }
    }
}

// x (fp32) -> fp16
__global__ void convx_kernel(const float* __restrict__ x, __half* __restrict__ xh, size_t n4) {
    size_t i = (size_t)blockIdx.x * blockDim.x + threadIdx.x;
    size_t stride = (size_t)gridDim.x * blockDim.x;
    for (; i < n4; i += stride) {
        float4 v = ((const float4*)x)[i];
        __half2* o = (__half2*)(xh + i * 4);
        o[0] = __floats2half2_rn(v.x, v.y);
        o[1] = __floats2half2_rn(v.z, v.w);
    }
}

// transpose [e][R][C] fp32 -> [e][C][R] fp16
__global__ void transpose_h_kernel(const float* __restrict__ src,
                                   __half* __restrict__ dst, int R, int C) {
    __shared__ float tile[32][33];
    int e = blockIdx.z;
    size_t off = (size_t)e * R * C;
    int c0 = blockIdx.x * 32, r0 = blockIdx.y * 32;
    int tx = threadIdx.x, ty = threadIdx.y;
#pragma unroll
    for (int i = 0; i < 32; i += 8)
        tile[ty + i][tx] = src[off + (size_t)(r0 + ty + i) * C + c0 + tx];
    __syncthreads();
#pragma unroll
    for (int i = 0; i < 32; i += 8)
        dst[off + (size_t)(c0 + ty + i) * R + r0 + tx] = __float2half(tile[tx][ty + i]);
}

// ===========================================================================
// fp16 mma.sync GEMM, 128x256 tile, 8 warps (2x4), 64x64 warp tile.
//   MODE 0: g_Hh[base+r,:] = relu(fp16(x)[tok[r],:] @ W1t^T + b1)   K=DIN
//   MODE 1: out[tok[r],:] += w[r] * (g_Hh[base+r,:] @ W2t^T + b2)   K=DH
// ===========================================================================
template <int MODE>
__global__ void __launch_bounds__(256, 1)
moe_gemm_h(const __half* __restrict__ Ah,
           const __half* __restrict__ Wt,   // [e][n][k] fp16
           const float* __restrict__ bias,
           float* __restrict__ outp)
{
    constexpr int K = MODE ? DH : DIN;
    constexpr int NDIM = MODE ? DOUT : DH;
    constexpr int NI = K / BK;

    const int e = blockIdx.z;
    const int cnt = g_cnt[e];
    const int row0 = blockIdx.y * BM;
    if (row0 >= cnt) return;
    const int n0 = blockIdx.x * BN;

    extern __shared__ char smem[];
    __shared__ int   toks[BM];
    __shared__ float wts[BM];
    const uint32_t sb = smem_u32(smem);

    const int tid = threadIdx.x, wid = tid >> 5, lane = tid & 31;
    const int warpM = wid & 1, warpN = wid >> 1;      // 2 x 4
    const int basee = g_base[e];

    if (tid < BM) {
        int r = row0 + tid;
        int rc = (r < cnt) ? r : (cnt - 1);
        toks[tid] = g_tok[e * T_TOK + rc];
        wts[tid] = (MODE && r < cnt) ? g_wt[e * T_TOK + r] : 0.f;
    }
    __syncthreads();

    // ---- cp.async: A = half row per thread (2 chunks), B = one row per thread (4 chunks)
    const int arow = tid >> 1;
    const int ac0 = tid & 1, ac1 = ac0 + 2;
    const __half* aptr;
    if (MODE == 0) {
        aptr = Ah + (size_t)toks[arow] * DIN;
    } else {
        int rr = row0 + arow; if (rr >= cnt) rr = cnt - 1;
        aptr = Ah + (size_t)(basee + rr) * DH;
    }
    const __half* bptr = Wt + (size_t)e * NDIM * K + (size_t)(n0 + tid) * K;
    const uint32_t da0 = sb + arow * ROWB + ac0 * 16;
    const uint32_t da1 = sb + arow * ROWB + ac1 * 16;
    const uint32_t dbb = sb + A_STG + tid * ROWB;

#define ISSUE(s, kidx) do {                             \
        uint32_t so_ = (uint32_t)(s) * STG;             \
        const __half* a_ = aptr + (kidx);               \
        const __half* b_ = bptr + (kidx);               \
        CP16(da0 + so_, a_ + ac0 * 8);                  \
        CP16(da1 + so_, a_ + ac1 * 8);                  \
        CP16(dbb + so_ +  0, b_ +  0);                  \
        CP16(dbb + so_ + 16, b_ +  8);                  \
        CP16(dbb + so_ + 32, b_ + 16);                  \
        CP16(dbb + so_ + 48, b_ + 24);                  \
    } while (0)

    // ---- ldmatrix per-lane base offsets
    const uint32_t a_off = sb + (uint32_t)((warpM * 64 + (lane & 15)) * ROWB + (lane >> 4) * 16);
    const uint32_t b_off = sb + A_STG +
        (uint32_t)((warpN * 64 + ((lane >> 4) << 3) + (lane & 7)) * ROWB + ((lane >> 3) & 1) * 16);

    float acc[4][8][4];
#pragma unroll
    for (int m = 0; m < 4; m++)
#pragma unroll
        for (int j = 0; j < 8; j++)
#pragma unroll
            for (int r = 0; r < 4; r++) acc[m][j][r] = 0.f;

    // prologue: 3 stages in flight
    ISSUE(0, 0);  CP_COMMIT();
    ISSUE(1, BK); CP_COMMIT();
    ISSUE(2, 2 * BK); CP_COMMIT();

#pragma unroll 1
    for (int i = 0; i < NI; i++) {
        CP_WAIT2();
        __syncthreads();
        if (i + 3 < NI) ISSUE((i + 3) & 3, (i + 3) * BK);
        CP_COMMIT();
        const uint32_t so = (uint32_t)(i & 3) * STG;
#pragma unroll
        for (int ks = 0; ks < 2; ks++) {
            uint32_t a[4][4], b[4][4];
#pragma unroll
            for (int m = 0; m < 4; m++)
                LDSM4(a[m], a_off + so + m * (16 * ROWB) + ks * 32);
#pragma unroll
            for (int t = 0; t < 4; t++)
                LDSM4(b[t], b_off + so + t * (16 * ROWB) + ks * 32);
#pragma unroll
            for (int m = 0; m < 4; m++)
#pragma unroll
                for (int t = 0; t < 4; t++) {
                    MMA16816(acc[m][2 * t],     a[m], b[t][0], b[t][1]);
                    MMA16816(acc[m][2 * t + 1], a[m], b[t][2], b[t][3]);
                }
        }
    }
#undef ISSUE

    // ---- epilogue ----
#pragma unroll
    for (int j = 0; j < 8; j++) {
        const int col = n0 + warpN * 64 + j * 8 + (lane & 3) * 2;
        const float bb0 = bias[(size_t)e * NDIM + col];
        const float bb1 = bias[(size_t)e * NDIM + col + 1];
#pragma unroll
        for (int m = 0; m < 4; m++) {
            const int rl = warpM * 64 + m * 16 + (lane >> 2);
            if (MODE == 0) {
                if (row0 + rl < cnt) {
                    __half2 h = __floats2half2_rn(fmaxf(acc[m][j][0] + bb0, 0.f),
                                                  fmaxf(acc[m][j][1] + bb1, 0.f));
                    *(__half2*)(g_Hh + (size_t)(basee + row0 + rl) * DH + col) = h;
                }
                if (row0 + rl + 8 < cnt) {
                    __half2 h = __floats2half2_rn(fmaxf(acc[m][j][2] + bb0, 0.f),
                                                  fmaxf(acc[m][j][3] + bb1, 0.f));
                    *(__half2*)(g_Hh + (size_t)(basee + row0 + rl + 8) * DH + col) = h;
                }
            } else {
                if (row0 + rl < cnt) {
                    int tk = toks[rl]; float w = wts[rl];
                    float* o = outp + (size_t)tk * DOUT + col;
                    atomicAdd(o,     w * (acc[m][j][0] + bb0));
                    atomicAdd(o + 1, w * (acc[m][j][1] + bb1));
                }
                if (row0 + rl + 8 < cnt) {
                    int tk = toks[rl + 8]; float w = wts[rl + 8];
                    float* o = outp + (size_t)tk * DOUT + col;
                    atomicAdd(o,     w * (acc[m][j][2] + bb0));
                    atomicAdd(o + 1, w * (acc[m][j][3] + bb1));
                }
            }
        }
    }
}

// ===========================================================================
extern "C" void kernel_launch(void* const* d_in, const int* in_sizes, int n_in,
                              void* d_out, int out_size) {
    (void)in_sizes; (void)n_in; (void)out_size;
    const float* x  = (const float*)d_in[0];
    const float* Wg = (const float*)d_in[1];
    const float* bg = (const float*)d_in[2];
    const float* W1 = (const float*)d_in[3];
    const float* b1 = (const float*)d_in[4];
    const float* W2 = (const float*)d_in[5];
    const float* b2 = (const float*)d_in[6];
    float* out = (float*)d_out;

    cudaFuncSetAttribute(moe_gemm_h<0>, cudaFuncAttributeMaxDynamicSharedMemorySize, SMEM_BYTES);
    cudaFuncSetAttribute(moe_gemm_h<1>, cudaFuncAttributeMaxDynamicSharedMemorySize, SMEM_BYTES);

    __half* xh;  cudaGetSymbolAddress((void**)&xh,  g_xh);
    __half* Hh;  cudaGetSymbolAddress((void**)&Hh,  g_Hh);
    __half* W1t; cudaGetSymbolAddress((void**)&W1t, g_W1th);
    __half* W2t; cudaGetSymbolAddress((void**)&W2t, g_W2th);

    zero_kernel<<<2048, 256>>>(out, (size_t)T_TOK * DOUT);
    gate_kernel<<<(T_TOK * 32 + 255) / 256, 256>>>(x, Wg, bg);
    prefix_kernel<<<1, 32>>>();
    convx_kernel<<<2048, 256>>>(x, xh, (size_t)T_TOK * DIN / 4);
    transpose_h_kernel<<<dim3(DH / 32, DIN / 32, NEXP), dim3(32, 8)>>>(W1, W1t, DIN, DH);
    transpose_h_kernel<<<dim3(DOUT / 32, DH / 32, NEXP), dim3(32, 8)>>>(W2, W2t, DH, DOUT);
    moe_gemm_h<0><<<dim3(DH / BN, T_TOK / BM, NEXP), 256, SMEM_BYTES>>>(xh, W1t, b1, nullptr);
    moe_gemm_h<1><<<dim3(DOUT / BN, T_TOK / BM, NEXP), 256, SMEM_BYTES>>>(Hh, W2t, b2, out);
}

// round 12
// speedup vs baseline: 1.1163x; 1.1163x over previous
#include <cuda_runtime.h>
#include <cuda_fp16.h>
#include <cstdint>

#define T_TOK 8192
#define NEXP 8
#define DIN 1024
#define DH 4096
#define DOUT 1024

#define BM 128
#define BN 128
#define BK 32              // fp16 elems per K-chunk
#define ROWB 80            // padded smem row bytes (32*2 + 16 pad) -> conflict-free ldmatrix
#define ASTG (BM * ROWB)   // 10240 B per stage (A); B same
#define NS 4
#define BOFF (NS * ASTG)   // B region offset = 40960
#define SMEM_BYTES (2 * NS * ASTG)  // 81920

// ---- device globals (no allocations allowed) ----
__device__ int    g_cnt[NEXP];
__device__ int    g_base[NEXP];
__device__ int    g_tok[NEXP * T_TOK];
__device__ float  g_wt [NEXP * T_TOK];
__device__ __half g_xh  [(size_t)T_TOK * DIN];            // 16 MB
__device__ __half g_Hh  [(size_t)(2 * T_TOK) * DH];       // 128 MB
__device__ __half g_W1th[(size_t)NEXP * DH * DIN];        // 64 MB  [e][n][k]
__device__ __half g_W2th[(size_t)NEXP * DOUT * DH];       // 64 MB  [e][o][h]

// ===========================================================================
// PTX helpers (base ISA only: cp.async / ldmatrix / mma.sync)
// ===========================================================================
__device__ __forceinline__ uint32_t smem_u32(const void* p) {
    uint32_t a;
    asm("{ .reg .u64 t; cvta.to.shared.u64 t, %1; cvt.u32.u64 %0, t; }"
        : "=r"(a) : "l"(p));
    return a;
}
#define CP16(dst, src) \
    asm volatile("cp.async.cg.shared.global [%0], [%1], 16;" \
        :: "r"(dst), "l"(src))
#define CP_COMMIT() asm volatile("cp.async.commit_group;" ::: "memory")
#define CP_WAIT2()  asm volatile("cp.async.wait_group 2;" ::: "memory")
#define LDSM4(r, addr) \
    asm volatile("ldmatrix.sync.aligned.m8n8.x4.shared.b16 {%0,%1,%2,%3}, [%4];" \
        : "=r"((r)[0]), "=r"((r)[1]), "=r"((r)[2]), "=r"((r)[3]) : "r"(addr))
#define MMA16816(c, a, b0v, b1v) \
    asm volatile("mma.sync.aligned.m16n8k16.row.col.f32.f16.f16.f32 " \
        "{%0,%1,%2,%3}, {%4,%5,%6,%7}, {%8,%9}, {%0,%1,%2,%3};" \
        : "+f"((c)[0]), "+f"((c)[1]), "+f"((c)[2]), "+f"((c)[3]) \
        : "r"((a)[0]), "r"((a)[1]), "r"((a)[2]), "r"((a)[3]), "r"(b0v), "r"(b1v))

// ===========================================================================
// small kernels
// ===========================================================================
__global__ void gate_kernel(const float* __restrict__ x,
                            const float* __restrict__ Wg,
                            const float* __restrict__ bg) {
    int t = (int)((blockIdx.x * blockDim.x + threadIdx.x) >> 5);
    int lane = threadIdx.x & 31;
    if (blockIdx.x == 0 && threadIdx.x < NEXP) g_cnt[threadIdx.x] = 0;  // reset before use
    __syncthreads();
    if (t >= T_TOK) return;
    const float* xr = x + (size_t)t * DIN;
    float acc[NEXP];
#pragma unroll
    for (int e = 0; e < NEXP; e++) acc[e] = 0.f;
    for (int k = lane; k < DIN; k += 32) {
        float xv = xr[k];
        const float4* wr = (const float4*)(Wg + (size_t)k * NEXP);
        float4 w0 = wr[0], w1 = wr[1];
        acc[0] += xv * w0.x; acc[1] += xv * w0.y;
        acc[2] += xv * w0.z; acc[3] += xv * w0.w;
        acc[4] += xv * w1.x; acc[5] += xv * w1.y;
        acc[6] += xv * w1.z; acc[7] += xv * w1.w;
    }
#pragma unroll
    for (int e = 0; e < NEXP; e++) {
#pragma unroll
        for (int off = 16; off; off >>= 1)
            acc[e] += __shfl_down_sync(0xffffffffu, acc[e], off);
    }
    if (lane == 0) {
#pragma unroll
        for (int e = 0; e < NEXP; e++) acc[e] += bg[e];
        int i0 = 0; float v0 = acc[0];
#pragma unroll
        for (int e = 1; e < NEXP; e++) if (acc[e] > v0) { v0 = acc[e]; i0 = e; }
        int i1 = -1; float v1 = -3.4e38f;
#pragma unroll
        for (int e = 0; e < NEXP; e++)
            if (e != i0 && acc[e] > v1) { v1 = acc[e]; i1 = e; }
        float w0 = 1.f / (1.f + expf(v1 - v0));
        float w1 = 1.f - w0;
        int s0 = atomicAdd(&g_cnt[i0], 1);
        g_tok[i0 * T_TOK + s0] = t; g_wt[i0 * T_TOK + s0] = w0;
        int s1 = atomicAdd(&g_cnt[i1], 1);
        g_tok[i1 * T_TOK + s1] = t; g_wt[i1 * T_TOK + s1] = w1;
    }
}

// NOTE: gate_kernel block 0 resets g_cnt, but OTHER blocks may race ahead.
// Safe ordering requires reset in a prior kernel; keep a tiny reset launch? No:
// fold the reset into the end of the PREVIOUS graph iteration is not allowed.
// Instead reset g_cnt in its own micro-kernel fused with nothing would add a
// launch. We keep correctness by resetting in a dedicated tiny kernel below.

__global__ void reset_kernel() {
    if (threadIdx.x < NEXP) g_cnt[threadIdx.x] = 0;
}

__global__ void prefix_kernel() {
    if (threadIdx.x == 0) {
        int s = 0;
#pragma unroll
        for (int e = 0; e < NEXP; e++) { g_base[e] = s; s += g_cnt[e]; }
    }
}

// fused: zero out[] + convert x fp32 -> fp16
__global__ void zeroconv_kernel(const float* __restrict__ x, __half* __restrict__ xh,
                                float* __restrict__ out, size_t n4x, size_t n4o) {
    size_t i = (size_t)blockIdx.x * blockDim.x + threadIdx.x;
    size_t stride = (size_t)gridDim.x * blockDim.x;
    for (size_t j = i; j < n4x; j += stride) {
        float4 v = ((const float4*)x)[j];
        __half2* o = (__half2*)(xh + j * 4);
        o[0] = __floats2half2_rn(v.x, v.y);
        o[1] = __floats2half2_rn(v.z, v.w);
    }
    float4 z = make_float4(0.f, 0.f, 0.f, 0.f);
    for (size_t j = i; j < n4o; j += stride) ((float4*)out)[j] = z;
}

// transpose [e][R][C] fp32 -> [e][C][R] fp16
__global__ void transpose_h_kernel(const float* __restrict__ src,
                                   __half* __restrict__ dst, int R, int C) {
    __shared__ float tile[32][33];
    int e = blockIdx.z;
    size_t off = (size_t)e * R * C;
    int c0 = blockIdx.x * 32, r0 = blockIdx.y * 32;
    int tx = threadIdx.x, ty = threadIdx.y;
#pragma unroll
    for (int i = 0; i < 32; i += 8)
        tile[ty + i][tx] = src[off + (size_t)(r0 + ty + i) * C + c0 + tx];
    __syncthreads();
#pragma unroll
    for (int i = 0; i < 32; i += 8)
        dst[off + (size_t)(c0 + ty + i) * R + r0 + tx] = __float2half(tile[tx][ty + i]);
}

// ===========================================================================
// fp16 mma.sync GEMM (R7 config: 128x128 tile, 8 warps 2x4, 2 CTA/SM).
//   MODE 0: g_Hh[base+r,:] = relu(fp16(x)[tok[r],:] @ W1t^T + b1)   K=DIN
//   MODE 1: out[tok[r],:] += w[r] * (g_Hh[base+r,:] @ W2t^T + b2)   K=DH
// ===========================================================================
template <int MODE>
__global__ void __launch_bounds__(256, 2)
moe_gemm_h(const __half* __restrict__ Ah,
           const __half* __restrict__ Wt,   // [e][n][k] fp16
           const float* __restrict__ bias,
           float* __restrict__ outp)
{
    constexpr int K = MODE ? DH : DIN;
    constexpr int NDIM = MODE ? DOUT : DH;
    constexpr int NI = K / BK;

    const int e = blockIdx.z;
    const int cnt = g_cnt[e];
    const int row0 = blockIdx.y * BM;
    if (row0 >= cnt) return;
    const int n0 = blockIdx.x * BN;

    extern __shared__ char smem[];
    __shared__ int   toks[BM];
    __shared__ float wts[BM];
    const uint32_t sb = smem_u32(smem);

    const int tid = threadIdx.x, wid = tid >> 5, lane = tid & 31;
    const int warpM = wid & 1, warpN = wid >> 1;
    const int basee = g_base[e];

    if (tid < BM) {
        int r = row0 + tid;
        int rc = (r < cnt) ? r : (cnt - 1);
        toks[tid] = g_tok[e * T_TOK + rc];
        wts[tid] = (MODE && r < cnt) ? g_wt[e * T_TOK + r] : 0.f;
    }
    __syncthreads();

    const int arow = tid >> 1;
    const int ac0 = tid & 1, ac1 = ac0 + 2;
    const __half* aptr;
    if (MODE == 0) {
        aptr = Ah + (size_t)toks[arow] * DIN;
    } else {
        int rr = row0 + arow; if (rr >= cnt) rr = cnt - 1;
        aptr = Ah + (size_t)(basee + rr) * DH;
    }
    const __half* bptr = Wt + (size_t)e * NDIM * K + (size_t)(n0 + arow) * K;
    const uint32_t da0 = sb + arow * ROWB + ac0 * 16;
    const uint32_t da1 = sb + arow * ROWB + ac1 * 16;
    const uint32_t db0 = sb + BOFF + arow * ROWB + ac0 * 16;
    const uint32_t db1 = sb + BOFF + arow * ROWB + ac1 * 16;

#define ISSUE(s, kidx) do {                             \
        uint32_t so_ = (uint32_t)(s) * ASTG;            \
        const __half* a_ = aptr + (kidx);               \
        const __half* b_ = bptr + (kidx);               \
        CP16(da0 + so_, a_ + ac0 * 8);                  \
        CP16(da1 + so_, a_ + ac1 * 8);                  \
        CP16(db0 + so_, b_ + ac0 * 8);                  \
        CP16(db1 + so_, b_ + ac1 * 8);                  \
    } while (0)

    const uint32_t a_off = sb + (uint32_t)((warpM * 64 + (lane & 15)) * ROWB + (lane >> 4) * 16);
    const uint32_t b_off = sb + BOFF +
        (uint32_t)((warpN * 32 + ((lane >> 4) << 3) + (lane & 7)) * ROWB + ((lane >> 3) & 1) * 16);

    float acc[4][4][4];
#pragma unroll
    for (int m = 0; m < 4; m++)
#pragma unroll
        for (int j = 0; j < 4; j++)
#pragma unroll
            for (int r = 0; r < 4; r++) acc[m][j][r] = 0.f;

    ISSUE(0, 0);  CP_COMMIT();
    ISSUE(1, BK); CP_COMMIT();
    ISSUE(2, 2 * BK); CP_COMMIT();

#pragma unroll 1
    for (int i = 0; i < NI; i++) {
        CP_WAIT2();
        __syncthreads();
        if (i + 3 < NI) ISSUE((i + 3) & 3, (i + 3) * BK);
        CP_COMMIT();
        const uint32_t so = (uint32_t)(i & 3) * ASTG;
#pragma unroll
        for (int ks = 0; ks < 2; ks++) {
            uint32_t a[4][4], b[2][4];
#pragma unroll
            for (int m = 0; m < 4; m++)
                LDSM4(a[m], a_off + so + m * (16 * ROWB) + ks * 32);
#pragma unroll
            for (int t = 0; t < 2; t++)
                LDSM4(b[t], b_off + so + t * (16 * ROWB) + ks * 32);
#pragma unroll
            for (int m = 0; m < 4; m++) {
                MMA16816(acc[m][0], a[m], b[0][0], b[0][1]);
                MMA16816(acc[m][1], a[m], b[0][2], b[0][3]);
                MMA16816(acc[m][2], a[m], b[1][0], b[1][1]);
                MMA16816(acc[m][3], a[m], b[1][2], b[1][3]);
            }
        }
    }
#undef ISSUE

#pragma unroll
    for (int j = 0; j < 4; j++) {
        const int col = n0 + warpN * 32 + j * 8 + (lane & 3) * 2;
        const float bb0 = bias[(size_t)e * NDIM + col];
        const float bb1 = bias[(size_t)e * NDIM + col + 1];
#pragma unroll
        for (int m = 0; m < 4; m++) {
            const int rl = warpM * 64 + m * 16 + (lane >> 2);
            if (MODE == 0) {
                if (row0 + rl < cnt) {
                    __half2 h = __floats2half2_rn(fmaxf(acc[m][j][0] + bb0, 0.f),
                                                  fmaxf(acc[m][j][1] + bb1, 0.f));
                    *(__half2*)(g_Hh + (size_t)(basee + row0 + rl) * DH + col) = h;
                }
                if (row0 + rl + 8 < cnt) {
                    __half2 h = __floats2half2_rn(fmaxf(acc[m][j][2] + bb0, 0.f),
                                                  fmaxf(acc[m][j][3] + bb1, 0.f));
                    *(__half2*)(g_Hh + (size_t)(basee + row0 + rl + 8) * DH + col) = h;
                }
            } else {
                if (row0 + rl < cnt) {
                    int tk = toks[rl]; float w = wts[rl];
                    float* o = outp + (size_t)tk * DOUT + col;
                    atomicAdd(o,     w * (acc[m][j][0] + bb0));
                    atomicAdd(o + 1, w * (acc[m][j][1] + bb1));
                }
                if (row0 + rl + 8 < cnt) {
                    int tk = toks[rl + 8]; float w = wts[rl + 8];
                    float* o = outp + (size_t)tk * DOUT + col;
                    atomicAdd(o,     w * (acc[m][j][2] + bb0));
                    atomicAdd(o + 1, w * (acc[m][j][3] + bb1));
                }
            }
        }
    }
}

// ===========================================================================
extern "C" void kernel_launch(void* const* d_in, const int* in_sizes, int n_in,
                              void* d_out, int out_size) {
    (void)in_sizes; (void)n_in; (void)out_size;
    const float* x  = (const float*)d_in[0];
    const float* Wg = (const float*)d_in[1];
    const float* bg = (const float*)d_in[2];
    const float* W1 = (const float*)d_in[3];
    const float* b1 = (const float*)d_in[4];
    const float* W2 = (const float*)d_in[5];
    const float* b2 = (const float*)d_in[6];
    float* out = (float*)d_out;

    cudaFuncSetAttribute(moe_gemm_h<0>, cudaFuncAttributeMaxDynamicSharedMemorySize, SMEM_BYTES);
    cudaFuncSetAttribute(moe_gemm_h<1>, cudaFuncAttributeMaxDynamicSharedMemorySize, SMEM_BYTES);

    __half* xh;  cudaGetSymbolAddress((void**)&xh,  g_xh);
    __half* Hh;  cudaGetSymbolAddress((void**)&Hh,  g_Hh);
    __half* W1t; cudaGetSymbolAddress((void**)&W1t, g_W1th);
    __half* W2t; cudaGetSymbolAddress((void**)&W2t, g_W2th);

    // launch order chosen so gemm1 is launch index 5 (ncu -s 5 -c 1 samples it)
    reset_kernel<<<1, 32>>>();                                                     // 0
    gate_kernel<<<(T_TOK * 32 + 255) / 256, 256>>>(x, Wg, bg);                     // 1
    prefix_kernel<<<1, 32>>>();                                                    // 2
    zeroconv_kernel<<<2048, 256>>>(x, xh, out, (size_t)T_TOK * DIN / 4,
                                   (size_t)T_TOK * DOUT / 4);                      // 3
    transpose_h_kernel<<<dim3(DH / 32, DIN / 32, NEXP), dim3(32, 8)>>>(W1, W1t, DIN, DH);   // 4
    moe_gemm_h<0><<<dim3(DH / BN, T_TOK / BM, NEXP), 256, SMEM_BYTES>>>(xh, W1t, b1, nullptr); // 5 <- profiled
    transpose_h_kernel<<<dim3(DOUT / 32, DH / 32, NEXP), dim3(32, 8)>>>(W2, W2t, DH, DOUT); // 6
    moe_gemm_h<1><<<dim3(DOUT / BN, T_TOK / BM, NEXP), 256, SMEM_BYTES>>>(Hh, W2t, b2, out);   // 7
}

// round 14
// speedup vs baseline: 1.1307x; 1.0129x over previous
#include <cuda_runtime.h>
#include <cuda_fp16.h>
#include <cstdint>

#define T_TOK 8192
#define NEXP 8
#define DIN 1024
#define DH 4096
#define DOUT 1024

#define BM 128
#define BN 128
#define BK 32              // fp16 elems per K-chunk
#define ROWB 80            // padded smem row bytes (32*2 + 16 pad) -> conflict-free ldmatrix
#define ASTG (BM * ROWB)   // 10240 B per stage (A); B same
#define NS 4
#define BOFF (NS * ASTG)   // B region offset = 40960
#define SMEM_BYTES (2 * NS * ASTG)  // 81920

// ---- device globals (no allocations allowed) ----
__device__ int    g_cnt[NEXP];
__device__ int    g_base[NEXP];
__device__ int    g_tok[NEXP * T_TOK];
__device__ float  g_wt [NEXP * T_TOK];
__device__ __half g_xh  [(size_t)T_TOK * DIN];            // 16 MB
__device__ __half g_Hh  [(size_t)(2 * T_TOK) * DH];       // 128 MB
__device__ __half g_W1th[(size_t)NEXP * DH * DIN];        // 64 MB  [e][n][k]
__device__ __half g_W2th[(size_t)NEXP * DOUT * DH];       // 64 MB  [e][o][h]

// ===========================================================================
// PTX helpers (base ISA only: cp.async / ldmatrix / mma.sync)
// ===========================================================================
__device__ __forceinline__ uint32_t smem_u32(const void* p) {
    uint32_t a;
    asm("{ .reg .u64 t; cvta.to.shared.u64 t, %1; cvt.u32.u64 %0, t; }"
        : "=r"(a) : "l"(p));
    return a;
}
#define CP16(dst, src) \
    asm volatile("cp.async.cg.shared.global [%0], [%1], 16;" \
        :: "r"(dst), "l"(src))
#define CP_COMMIT() asm volatile("cp.async.commit_group;" ::: "memory")
#define CP_WAIT2()  asm volatile("cp.async.wait_group 2;" ::: "memory")
#define LDSM4(r, addr) \
    asm volatile("ldmatrix.sync.aligned.m8n8.x4.shared.b16 {%0,%1,%2,%3}, [%4];" \
        : "=r"((r)[0]), "=r"((r)[1]), "=r"((r)[2]), "=r"((r)[3]) : "r"(addr))
#define MMA16816(c, a, b0v, b1v) \
    asm volatile("mma.sync.aligned.m16n8k16.row.col.f32.f16.f16.f32 " \
        "{%0,%1,%2,%3}, {%4,%5,%6,%7}, {%8,%9}, {%0,%1,%2,%3};" \
        : "+f"((c)[0]), "+f"((c)[1]), "+f"((c)[2]), "+f"((c)[3]) \
        : "r"((a)[0]), "r"((a)[1]), "r"((a)[2]), "r"((a)[3]), "r"(b0v), "r"(b1v))

// ===========================================================================
// prep: fused reset(g_cnt) + zero(out) + conv(x->fp16) + transpose W1,W2
// block regions:
//   [0, 32768)           : W1 transpose tiles   (e=blk/4096, ry=(blk%4096)/128, cx=blk%128)
//   [32768, 65536)       : W2 transpose tiles   (e=.../4096, ry=(rem)/32,  cx=rem%32)
//   [65536, 67584)       : zero out + conv x (2048 blocks, grid-stride)
// ===========================================================================
__device__ __forceinline__ void transpose_tile(const float* __restrict__ src,
                                               __half* __restrict__ dst,
                                               int R, int C, int e, int ry, int cx,
                                               int tx, int ty) {
    __shared__ float tile[32][33];
    size_t off = (size_t)e * R * C;
    int c0 = cx * 32, r0 = ry * 32;
#pragma unroll
    for (int i = 0; i < 32; i += 8)
        tile[ty + i][tx] = src[off + (size_t)(r0 + ty + i) * C + c0 + tx];
    __syncthreads();
#pragma unroll
    for (int i = 0; i < 32; i += 8)
        dst[off + (size_t)(c0 + ty + i) * R + r0 + tx] = __float2half(tile[tx][ty + i]);
}

__global__ void prep_kernel(const float* __restrict__ x,
                            const float* __restrict__ W1,
                            const float* __restrict__ W2,
                            float* __restrict__ out) {
    const int nb = blockIdx.x;
    const int tid = threadIdx.x;
    const int tx = tid & 31, ty = tid >> 5;

    if (nb < 32768) {                       // W1: R=DIN, C=DH
        int e = nb >> 12, rem = nb & 4095;
        transpose_tile(W1, g_W1th, DIN, DH, e, rem >> 7, rem & 127, tx, ty);
    } else if (nb < 65536) {                // W2: R=DH, C=DOUT
        int b = nb - 32768;
        int e = b >> 12, rem = b & 4095;
        transpose_tile(W2, g_W2th, DH, DOUT, e, rem >> 5, rem & 31, tx, ty);
    } else {
        int b = nb - 65536;                 // 2048 blocks
        size_t i = (size_t)b * 256 + tid;
        size_t stride = (size_t)2048 * 256;
        const size_t n4x = (size_t)T_TOK * DIN / 4;
        const size_t n4o = (size_t)T_TOK * DOUT / 4;
        for (size_t j = i; j < n4x; j += stride) {
            float4 v = ((const float4*)x)[j];
            __half2* o = (__half2*)(g_xh + j * 4);
            o[0] = __floats2half2_rn(v.x, v.y);
            o[1] = __floats2half2_rn(v.z, v.w);
        }
        float4 z = make_float4(0.f, 0.f, 0.f, 0.f);
        for (size_t j = i; j < n4o; j += stride) ((float4*)out)[j] = z;
        if (b == 0 && tid < NEXP) g_cnt[tid] = 0;
    }
}

// ===========================================================================
__global__ void gate_kernel(const float* __restrict__ x,
                            const float* __restrict__ Wg,
                            const float* __restrict__ bg) {
    int t = (int)((blockIdx.x * blockDim.x + threadIdx.x) >> 5);
    int lane = threadIdx.x & 31;
    if (t >= T_TOK) return;
    const float* xr = x + (size_t)t * DIN;
    float acc[NEXP];
#pragma unroll
    for (int e = 0; e < NEXP; e++) acc[e] = 0.f;
    for (int k = lane; k < DIN; k += 32) {
        float xv = xr[k];
        const float4* wr = (const float4*)(Wg + (size_t)k * NEXP);
        float4 w0 = wr[0], w1 = wr[1];
        acc[0] += xv * w0.x; acc[1] += xv * w0.y;
        acc[2] += xv * w0.z; acc[3] += xv * w0.w;
        acc[4] += xv * w1.x; acc[5] += xv * w1.y;
        acc[6] += xv * w1.z; acc[7] += xv * w1.w;
    }
#pragma unroll
    for (int e = 0; e < NEXP; e++) {
#pragma unroll
        for (int off = 16; off; off >>= 1)
            acc[e] += __shfl_down_sync(0xffffffffu, acc[e], off);
    }
    if (lane == 0) {
#pragma unroll
        for (int e = 0; e < NEXP; e++) acc[e] += bg[e];
        int i0 = 0; float v0 = acc[0];
#pragma unroll
        for (int e = 1; e < NEXP; e++) if (acc[e] > v0) { v0 = acc[e]; i0 = e; }
        int i1 = -1; float v1 = -3.4e38f;
#pragma unroll
        for (int e = 0; e < NEXP; e++)
            if (e != i0 && acc[e] > v1) { v1 = acc[e]; i1 = e; }
        float w0 = 1.f / (1.f + expf(v1 - v0));
        float w1 = 1.f - w0;
        int s0 = atomicAdd(&g_cnt[i0], 1);
        g_tok[i0 * T_TOK + s0] = t; g_wt[i0 * T_TOK + s0] = w0;
        int s1 = atomicAdd(&g_cnt[i1], 1);
        g_tok[i1 * T_TOK + s1] = t; g_wt[i1 * T_TOK + s1] = w1;
    }
}

__global__ void prefix_kernel() {
    if (threadIdx.x == 0) {
        int s = 0;
#pragma unroll
        for (int e = 0; e < NEXP; e++) { g_base[e] = s; s += g_cnt[e]; }
    }
}

// ===========================================================================
// fp16 mma.sync GEMM (128x128 tile, 8 warps 2x4, 2 CTA/SM).
//   MODE 0: g_Hh[base+r,:] = relu(fp16(x)[tok[r],:] @ W1t^T + b1)   K=DIN
//   MODE 1: out[tok[r],:] += w[r] * (g_Hh[base+r,:] @ W2t^T + b2)   K=DH
// ===========================================================================
template <int MODE>
__global__ void __launch_bounds__(256, 2)
moe_gemm_h(const __half* __restrict__ Ah,
           const __half* __restrict__ Wt,   // [e][n][k] fp16
           const float* __restrict__ bias,
           float* __restrict__ outp)
{
    constexpr int K = MODE ? DH : DIN;
    constexpr int NDIM = MODE ? DOUT : DH;
    constexpr int NI = K / BK;

    const int e = blockIdx.z;
    const int cnt = g_cnt[e];
    const int row0 = blockIdx.y * BM;
    if (row0 >= cnt) return;
    const int n0 = blockIdx.x * BN;

    extern __shared__ char smem[];
    __shared__ int   toks[BM];
    __shared__ float wts[BM];
    const uint32_t sb = smem_u32(smem);

    const int tid = threadIdx.x, wid = tid >> 5, lane = tid & 31;
    const int warpM = wid & 1, warpN = wid >> 1;
    const int basee = g_base[e];

    if (tid < BM) {
        int r = row0 + tid;
        int rc = (r < cnt) ? r : (cnt - 1);
        toks[tid] = g_tok[e * T_TOK + rc];
        wts[tid] = (MODE && r < cnt) ? g_wt[e * T_TOK + r] : 0.f;
    }
    __syncthreads();

    const int arow = tid >> 1;
    const int ac0 = tid & 1, ac1 = ac0 + 2;
    const __half* aptr;
    if (MODE == 0) {
        aptr = Ah + (size_t)toks[arow] * DIN;
    } else {
        int rr = row0 + arow; if (rr >= cnt) rr = cnt - 1;
        aptr = Ah + (size_t)(basee + rr) * DH;
    }
    const __half* bptr = Wt + (size_t)e * NDIM * K + (size_t)(n0 + arow) * K;
    const uint32_t da0 = sb + arow * ROWB + ac0 * 16;
    const uint32_t da1 = sb + arow * ROWB + ac1 * 16;
    const uint32_t db0 = sb + BOFF + arow * ROWB + ac0 * 16;
    const uint32_t db1 = sb + BOFF + arow * ROWB + ac1 * 16;

#define ISSUE(s, kidx) do {                             \
        uint32_t so_ = (uint32_t)(s) * ASTG;            \
        const __half* a_ = aptr + (kidx);               \
        const __half* b_ = bptr + (kidx);               \
        CP16(da0 + so_, a_ + ac0 * 8);                  \
        CP16(da1 + so_, a_ + ac1 * 8);                  \
        CP16(db0 + so_, b_ + ac0 * 8);                  \
        CP16(db1 + so_, b_ + ac1 * 8);                  \
    } while (0)

    const uint32_t a_off = sb + (uint32_t)((warpM * 64 + (lane & 15)) * ROWB + (lane >> 4) * 16);
    const uint32_t b_off = sb + BOFF +
        (uint32_t)((warpN * 32 + ((lane >> 4) << 3) + (lane & 7)) * ROWB + ((lane >> 3) & 1) * 16);

    float acc[4][4][4];
#pragma unroll
    for (int m = 0; m < 4; m++)
#pragma unroll
        for (int j = 0; j < 4; j++)
#pragma unroll
            for (int r = 0; r < 4; r++) acc[m][j][r] = 0.f;

    ISSUE(0, 0);  CP_COMMIT();
    ISSUE(1, BK); CP_COMMIT();
    ISSUE(2, 2 * BK); CP_COMMIT();

#pragma unroll 1
    for (int i = 0; i < NI; i++) {
        CP_WAIT2();
        __syncthreads();
        if (i + 3 < NI) ISSUE((i + 3) & 3, (i + 3) * BK);
        CP_COMMIT();
        const uint32_t so = (uint32_t)(i & 3) * ASTG;
#pragma unroll
        for (int ks = 0; ks < 2; ks++) {
            uint32_t a[4][4], b[2][4];
#pragma unroll
            for (int m = 0; m < 4; m++)
                LDSM4(a[m], a_off + so + m * (16 * ROWB) + ks * 32);
#pragma unroll
            for (int t = 0; t < 2; t++)
                LDSM4(b[t], b_off + so + t * (16 * ROWB) + ks * 32);
#pragma unroll
            for (int m = 0; m < 4; m++) {
                MMA16816(acc[m][0], a[m], b[0][0], b[0][1]);
                MMA16816(acc[m][1], a[m], b[0][2], b[0][3]);
                MMA16816(acc[m][2], a[m], b[1][0], b[1][1]);
                MMA16816(acc[m][3], a[m], b[1][2], b[1][3]);
            }
        }
    }
#undef ISSUE

#pragma unroll
    for (int j = 0; j < 4; j++) {
        const int col = n0 + warpN * 32 + j * 8 + (lane & 3) * 2;
        const float bb0 = bias[(size_t)e * NDIM + col];
        const float bb1 = bias[(size_t)e * NDIM + col + 1];
#pragma unroll
        for (int m = 0; m < 4; m++) {
            const int rl = warpM * 64 + m * 16 + (lane >> 2);
            if (MODE == 0) {
                if (row0 + rl < cnt) {
                    __half2 h = __floats2half2_rn(fmaxf(acc[m][j][0] + bb0, 0.f),
                                                  fmaxf(acc[m][j][1] + bb1, 0.f));
                    *(__half2*)(g_Hh + (size_t)(basee + row0 + rl) * DH + col) = h;
                }
                if (row0 + rl + 8 < cnt) {
                    __half2 h = __floats2half2_rn(fmaxf(acc[m][j][2] + bb0, 0.f),
                                                  fmaxf(acc[m][j][3] + bb1, 0.f));
                    *(__half2*)(g_Hh + (size_t)(basee + row0 + rl + 8) * DH + col) = h;
                }
            } else {
                if (row0 + rl < cnt) {
                    int tk = toks[rl]; float w = wts[rl];
                    float* o = outp + (size_t)tk * DOUT + col;
                    atomicAdd(o,     w * (acc[m][j][0] + bb0));
                    atomicAdd(o + 1, w * (acc[m][j][1] + bb1));
                }
                if (row0 + rl + 8 < cnt) {
                    int tk = toks[rl + 8]; float w = wts[rl + 8];
                    float* o = outp + (size_t)tk * DOUT + col;
                    atomicAdd(o,     w * (acc[m][j][2] + bb0));
                    atomicAdd(o + 1, w * (acc[m][j][3] + bb1));
                }
            }
        }
    }
}

// ===========================================================================
extern "C" void kernel_launch(void* const* d_in, const int* in_sizes, int n_in,
                              void* d_out, int out_size) {
    (void)in_sizes; (void)n_in; (void)out_size;
    const float* x  = (const float*)d_in[0];
    const float* Wg = (const float*)d_in[1];
    const float* bg = (const float*)d_in[2];
    const float* W1 = (const float*)d_in[3];
    const float* b1 = (const float*)d_in[4];
    const float* W2 = (const float*)d_in[5];
    const float* b2 = (const float*)d_in[6];
    float* out = (float*)d_out;

    cudaFuncSetAttribute(moe_gemm_h<0>, cudaFuncAttributeMaxDynamicSharedMemorySize, SMEM_BYTES);
    cudaFuncSetAttribute(moe_gemm_h<1>, cudaFuncAttributeMaxDynamicSharedMemorySize, SMEM_BYTES);

    __half* xh;  cudaGetSymbolAddress((void**)&xh,  g_xh);
    __half* Hh;  cudaGetSymbolAddress((void**)&Hh,  g_Hh);
    __half* W1t; cudaGetSymbolAddress((void**)&W1t, g_W1th);
    __half* W2t; cudaGetSymbolAddress((void**)&W2t, g_W2th);

    // gemm1 at launch index 3 (observed ncu sampling position)
    prep_kernel<<<67584, 256>>>(x, W1, W2, out);                                   // 0
    gate_kernel<<<(T_TOK * 32 + 255) / 256, 256>>>(x, Wg, bg);                     // 1
    prefix_kernel<<<1, 32>>>();                                                    // 2
    moe_gemm_h<0><<<dim3(DH / BN, T_TOK / BM, NEXP), 256, SMEM_BYTES>>>(xh, W1t, b1, nullptr); // 3 <- profiled
    moe_gemm_h<1><<<dim3(DOUT / BN, T_TOK / BM, NEXP), 256, SMEM_BYTES>>>(Hh, W2t, b2, out);   // 4
}